// round 2
// baseline (speedup 1.0000x reference)
#include <cuda_runtime.h>

#define NN 100000
#define NE 3200000
#define F  64

// Scratch (no allocations allowed)
__device__ __align__(16) float g_dis[NN];        // deg -> d^-1/2
__device__ __align__(16) float g_acc2[NN * 2];   // layer-1 aggregation of raw x
__device__ __align__(16) float g_h1[NN * F];     // layer-1 output (post-ReLU)
__device__ __align__(16) float g_acc64[NN * F];  // layer-2 aggregation of h1
__device__ float g_red;                          // global reduction scalar
__device__ int   g_is64;                         // edge_index dtype flag

__device__ __forceinline__ void red_add_f32(float* p, float v) {
    asm volatile("red.global.add.f32 [%0], %1;" :: "l"(p), "f"(v) : "memory");
}
__device__ __forceinline__ void red_add_v2(float* p, float a, float b) {
    asm volatile("red.global.add.v2.f32 [%0], {%1,%2};"
                 :: "l"(p), "f"(a), "f"(b) : "memory");
}
__device__ __forceinline__ void red_add_v4(float* p, float a, float b, float c, float d) {
    asm volatile("red.global.add.v4.f32 [%0], {%1,%2,%3,%4};"
                 :: "l"(p), "f"(a), "f"(b), "f"(c), "f"(d) : "memory");
}

// Load edge index element `e` (element offset, works for src or dst regions)
__device__ __forceinline__ int load_idx(const void* ei, long long e, int is64) {
    if (is64) return (int)((const long long*)ei)[e];
    return ((const int*)ei)[e];
}

// 0. dtype detection: if first 64 int64-interpreted values are all in range,
//    the buffer really is int64; otherwise it's int32.
__global__ void k_detect(const long long* __restrict__ ei) {
    int is64 = 1;
    for (int i = 0; i < 64; i++) {
        long long v = ei[i];
        if (v < 0 || v >= NN) { is64 = 0; break; }
    }
    g_is64 = is64;
}

// 1. init: deg=1 (self loop), zero acc2, zero reduction scalar
__global__ void k_init() {
    int i = blockIdx.x * blockDim.x + threadIdx.x;
    if (i < NN) {
        g_dis[i] = 1.0f;
        g_acc2[2 * i] = 0.0f;
        g_acc2[2 * i + 1] = 0.0f;
        if (i == 0) g_red = 0.0f;
    }
}

// 2. degree count over edge targets (dst = elements [NE, 2*NE))
__global__ void k_deg_edges(const void* __restrict__ ei) {
    int e = blockIdx.x * blockDim.x + threadIdx.x;
    if (e >= NE) return;
    int is64 = g_is64;
    int d = load_idx(ei, (long long)NE + e, is64);
    red_add_f32(&g_dis[d], 1.0f);
}

// 3. deg -> d^-1/2
__global__ void k_deg_fin() {
    int i = blockIdx.x * blockDim.x + threadIdx.x;
    if (i < NN) g_dis[i] = rsqrtf(g_dis[i]);
}

// 4. layer-1 scatter: aggregate raw 2-dim features (aggregate-then-transform)
__global__ void k_scatter2(const void* __restrict__ ei,
                           const float* __restrict__ x) {
    int e = blockIdx.x * blockDim.x + threadIdx.x;
    if (e >= NE) return;
    int is64 = g_is64;
    int s = load_idx(ei, e, is64);
    int d = load_idx(ei, (long long)NE + e, is64);
    float norm = g_dis[s] * g_dis[d];
    float2 v = reinterpret_cast<const float2*>(x)[s];
    red_add_v2(g_acc2 + 2 * d, v.x * norm, v.y * norm);
}

// 5. layer-1 dense: h1 = relu((agg + x*dis^2) @ W1 + b1); zero acc64
__global__ void k_layer1(const float* __restrict__ x,
                         const float* __restrict__ W1,
                         const float* __restrict__ b1) {
    int idx = blockIdx.x * blockDim.x + threadIdx.x;
    if (idx >= NN * F) return;
    int i = idx >> 6, c = idx & 63;
    float di = g_dis[i];
    float d2 = di * di;
    float a0 = g_acc2[2 * i]     + x[2 * i]     * d2;
    float a1 = g_acc2[2 * i + 1] + x[2 * i + 1] * d2;
    float v  = fmaf(a0, W1[c], fmaf(a1, W1[64 + c], b1[c]));
    g_h1[idx]    = fmaxf(v, 0.0f);
    g_acc64[idx] = 0.0f;
}

// 6. layer-2 scatter: 16 float4 chunks per edge, vector RED into acc64
__global__ void k_scatter64(const void* __restrict__ ei) {
    unsigned idx = blockIdx.x * blockDim.x + threadIdx.x;
    if (idx >= (unsigned)NE * 16u) return;
    int e = idx >> 4, c = idx & 15;
    int is64 = g_is64;
    int s = load_idx(ei, e, is64);
    int d = load_idx(ei, (long long)NE + e, is64);
    float norm = g_dis[s] * g_dis[d];
    float4 v = reinterpret_cast<const float4*>(g_h1)[s * 16 + c];
    red_add_v4(g_acc64 + (size_t)d * 64 + c * 4,
               v.x * norm, v.y * norm, v.z * norm, v.w * norm);
}

// 7. fused layer-2 dense + ReLU + mean-pool dot with Wl
//    block = 256 threads handles 32 rows (8 groups of 4); h2 never stored.
__global__ void k_layer2_reduce(const float* __restrict__ W2,
                                const float* __restrict__ b2,
                                const float* __restrict__ Wl) {
    __shared__ float sW[64 * 64];
    __shared__ float sh[4][64];
    __shared__ float sred[8];

    int t = threadIdx.x;
    for (int j = t; j < 4096; j += 256) sW[j] = W2[j];

    int r = t >> 6, c = t & 63;
    float bc  = b2[c];
    float wlc = Wl[c];
    int base = blockIdx.x * 32;

    float partial = 0.0f;
    for (int g = 0; g < 8; g++) {
        int i = base + g * 4 + r;          // NN % 32 == 0, always valid
        float di = g_dis[i];
        float d2 = di * di;
        __syncthreads();                   // protect sh reuse; also fences sW on g==0
        sh[r][c] = g_acc64[i * 64 + c] + g_h1[i * 64 + c] * d2;
        __syncthreads();
        float m = bc;
        #pragma unroll
        for (int k = 0; k < 64; k++) m = fmaf(sh[r][k], sW[k * 64 + c], m);
        partial += fmaxf(m, 0.0f) * wlc;
    }

    // block reduce
    #pragma unroll
    for (int o = 16; o; o >>= 1) partial += __shfl_down_sync(0xffffffffu, partial, o);
    if ((t & 31) == 0) sred[t >> 5] = partial;
    __syncthreads();
    if (t < 8) {
        float v = sred[t];
        #pragma unroll
        for (int o = 4; o; o >>= 1) v += __shfl_down_sync(0xffu, v, o);
        if (t == 0) atomicAdd(&g_red, v);
    }
}

// 8. final scalar
__global__ void k_final(const float* __restrict__ bl, float* __restrict__ out) {
    out[0] = g_red * (1.0f / NN) + bl[0];
}

extern "C" void kernel_launch(void* const* d_in, const int* in_sizes, int n_in,
                              void* d_out, int out_size) {
    const float* x  = (const float*)d_in[0];
    const void*  ei = d_in[1];
    const float* W1 = (const float*)d_in[2];
    const float* b1 = (const float*)d_in[3];
    const float* W2 = (const float*)d_in[4];
    const float* b2 = (const float*)d_in[5];
    const float* Wl = (const float*)d_in[6];
    const float* bl = (const float*)d_in[7];
    float* out = (float*)d_out;

    k_detect<<<1, 1>>>((const long long*)ei);
    k_init<<<(NN + 255) / 256, 256>>>();
    k_deg_edges<<<(NE + 255) / 256, 256>>>(ei);
    k_deg_fin<<<(NN + 255) / 256, 256>>>();
    k_scatter2<<<(NE + 255) / 256, 256>>>(ei, x);
    k_layer1<<<(NN * F + 255) / 256, 256>>>(x, W1, b1);
    k_scatter64<<<((unsigned)NE * 16u + 255u) / 256u, 256>>>(ei);
    k_layer2_reduce<<<NN / 32, 256>>>(W2, b2, Wl);
    k_final<<<1, 1>>>(bl, out);
}